// round 2
// baseline (speedup 1.0000x reference)
#include <cuda_runtime.h>

// Convex_f: out[b,j,k] = (interior && Dy>0) ? 0.5*(y[j-1]+y[j+1]) - param[j]
//                                          : y[j] - param[j]      // == reference's y - dy - param with dy=0
// where y = x + param, Dy = 2*y[j] - y[j-1] - y[j+1].
// Shapes: B=256, N=8192, K=16, float32, contiguous (B,N,K).

#ifndef CB
#define CB 256
#endif

constexpr int Bn = 256;
constexpr int Nn = 8192;
constexpr int Kn = 16;
constexpr int KV = Kn / 4;        // float4 lanes per (b,j) row = 4
constexpr int L  = 32;            // j-strip length per thread
constexpr int STRIPS = Nn / L;    // 256
// total threads = Bn * STRIPS * KV = 262144 -> 1024 blocks of 256

__device__ __forceinline__ float4 ld_stream(const float4* p) {
    return __ldcs(p);
}

__global__ __launch_bounds__(CB, 6)   // cap regs at 42 -> 6 blocks/SM (48 warps)
void convex_kernel(const float4* __restrict__ x4,
                   const float4* __restrict__ p4,
                   float4* __restrict__ o4)
{
    int tid   = blockIdx.x * CB + threadIdx.x;
    int kv    = tid & (KV - 1);                 // 0..3
    int strip = (tid >> 2) & (STRIPS - 1);      // 0..255
    int b     = tid >> 10;                      // /(KV*STRIPS)

    int base = b * (Nn * KV) + kv;              // float4 index of (b, j=0, kv)
    int j0   = strip * L;

    // Prologue: y[j0-1] (clamped; value unused when j0==0) and y[j0]
    int jm = (j0 > 0) ? (j0 - 1) : 0;
    float4 xm = ld_stream(&x4[base + jm * KV]);
    float4 pm = ld_stream(&p4[base + jm * KV]);
    float4 ym1 = make_float4(xm.x + pm.x, xm.y + pm.y, xm.z + pm.z, xm.w + pm.w);

    float4 x0 = ld_stream(&x4[base + j0 * KV]);
    float4 p0 = ld_stream(&p4[base + j0 * KV]);
    float4 y0 = make_float4(x0.x + p0.x, x0.y + p0.y, x0.z + p0.z, x0.w + p0.w);

    #pragma unroll
    for (int i = 0; i < L; i++) {
        int j  = j0 + i;
        int jn = (j + 1 < Nn) ? (j + 1) : j;    // clamp; value unused at j==N-1
        float4 xn = ld_stream(&x4[base + jn * KV]);
        float4 pn = ld_stream(&p4[base + jn * KV]);
        float4 yn = make_float4(xn.x + pn.x, xn.y + pn.y, xn.z + pn.z, xn.w + pn.w);

        bool interior = (j > 0) && (j < Nn - 1);

        float4 out;
        {
            float s    = ym1.x + yn.x;
            float Dy   = fmaf(2.0f, y0.x, -s);
            float alt  = fmaf(0.5f, s, -p0.x);
            float keep = y0.x - p0.x;
            out.x = (interior && Dy > 0.0f) ? alt : keep;
        }
        {
            float s    = ym1.y + yn.y;
            float Dy   = fmaf(2.0f, y0.y, -s);
            float alt  = fmaf(0.5f, s, -p0.y);
            float keep = y0.y - p0.y;
            out.y = (interior && Dy > 0.0f) ? alt : keep;
        }
        {
            float s    = ym1.z + yn.z;
            float Dy   = fmaf(2.0f, y0.z, -s);
            float alt  = fmaf(0.5f, s, -p0.z);
            float keep = y0.z - p0.z;
            out.z = (interior && Dy > 0.0f) ? alt : keep;
        }
        {
            float s    = ym1.w + yn.w;
            float Dy   = fmaf(2.0f, y0.w, -s);
            float alt  = fmaf(0.5f, s, -p0.w);
            float keep = y0.w - p0.w;
            out.w = (interior && Dy > 0.0f) ? alt : keep;
        }

        __stcs(&o4[base + j * KV], out);

        ym1 = y0; y0 = yn; p0 = pn;
    }
}

extern "C" void kernel_launch(void* const* d_in, const int* in_sizes, int n_in,
                              void* d_out, int out_size)
{
    const float4* x4 = (const float4*)d_in[0];
    const float4* p4 = (const float4*)d_in[1];
    float4* o4 = (float4*)d_out;

    int total_threads = Bn * STRIPS * KV;       // 262144
    int blocks = total_threads / CB;            // 1024
    convex_kernel<<<blocks, CB>>>(x4, p4, o4);
}

// round 3
// speedup vs baseline: 1.2815x; 1.2815x over previous
#include <cuda_runtime.h>

// Convex_f: out[b,j,k] = (interior && Dy>0) ? 0.5*(y[j-1]+y[j+1]) - param[j]
//                                          : y[j] - param[j]    // exact: (x+p)-p in fp32
// where y = x + param, Dy = 2*y[j] - y[j-1] - y[j+1].
// Shapes: B=256, N=8192, K=16, float32, contiguous (B,N,K).

#ifndef CB
#define CB 256
#endif

constexpr int Bn = 256;
constexpr int Nn = 8192;
constexpr int Kn = 16;
constexpr int KV = Kn / 4;        // float4 lanes per (b,j) row = 4
constexpr int L  = 32;            // j-strip length per thread
constexpr int STRIPS = Nn / L;    // 256
// total threads = Bn * STRIPS * KV = 262144 -> 1024 blocks of 256

__global__ __launch_bounds__(CB, 5)   // 48 regs -> 5 blocks/SM (40 warps), room to pipeline
void convex_kernel(const float4* __restrict__ x4,
                   const float4* __restrict__ p4,
                   float4* __restrict__ o4)
{
    int tid   = blockIdx.x * CB + threadIdx.x;
    int kv    = tid & (KV - 1);                 // 0..3
    int strip = (tid >> 2) & (STRIPS - 1);      // 0..255
    int b     = tid >> 10;                      // /(KV*STRIPS)

    int base = b * (Nn * KV) + kv;              // float4 index of (b, j=0, kv)
    int j0   = strip * L;

    // Prologue: y[j0-1] (clamped; value unused when j0==0) and y[j0]
    int jm = (j0 > 0) ? (j0 - 1) : 0;
    float4 xm = x4[base + jm * KV];
    float4 pm = p4[base + jm * KV];
    float4 ym1 = make_float4(xm.x + pm.x, xm.y + pm.y, xm.z + pm.z, xm.w + pm.w);

    float4 x0 = x4[base + j0 * KV];
    float4 p0 = p4[base + j0 * KV];
    float4 y0 = make_float4(x0.x + p0.x, x0.y + p0.y, x0.z + p0.z, x0.w + p0.w);

    // Prefetch buffer for j0+1
    float4 xa = x4[base + (j0 + 1) * KV];
    float4 pa = p4[base + (j0 + 1) * KV];

    #pragma unroll
    for (int i = 0; i < L; i++) {
        int j  = j0 + i;

        // Issue next prefetch (j+2) before consuming (j+1): keeps 2 loads in flight
        int jp = (j + 2 < Nn) ? (j + 2) : (Nn - 1);   // clamp; value unused at strip end
        float4 xb = x4[base + jp * KV];
        float4 pb = p4[base + jp * KV];

        float4 yn = make_float4(xa.x + pa.x, xa.y + pa.y, xa.z + pa.z, xa.w + pa.w);

        bool interior = (j > 0) && (j < Nn - 1);

        float4 out;
        {
            float s    = ym1.x + yn.x;
            float Dy   = fmaf(2.0f, y0.x, -s);
            float alt  = fmaf(0.5f, s, -p0.x);
            float keep = y0.x - p0.x;
            out.x = (interior && Dy > 0.0f) ? alt : keep;
        }
        {
            float s    = ym1.y + yn.y;
            float Dy   = fmaf(2.0f, y0.y, -s);
            float alt  = fmaf(0.5f, s, -p0.y);
            float keep = y0.y - p0.y;
            out.y = (interior && Dy > 0.0f) ? alt : keep;
        }
        {
            float s    = ym1.z + yn.z;
            float Dy   = fmaf(2.0f, y0.z, -s);
            float alt  = fmaf(0.5f, s, -p0.z);
            float keep = y0.z - p0.z;
            out.z = (interior && Dy > 0.0f) ? alt : keep;
        }
        {
            float s    = ym1.w + yn.w;
            float Dy   = fmaf(2.0f, y0.w, -s);
            float alt  = fmaf(0.5f, s, -p0.w);
            float keep = y0.w - p0.w;
            out.w = (interior && Dy > 0.0f) ? alt : keep;
        }

        o4[base + j * KV] = out;

        ym1 = y0; y0 = yn; p0 = pa;
        xa = xb; pa = pb;
    }
}

extern "C" void kernel_launch(void* const* d_in, const int* in_sizes, int n_in,
                              void* d_out, int out_size)
{
    const float4* x4 = (const float4*)d_in[0];
    const float4* p4 = (const float4*)d_in[1];
    float4* o4 = (float4*)d_out;

    int total_threads = Bn * STRIPS * KV;       // 262144
    int blocks = total_threads / CB;            // 1024
    convex_kernel<<<blocks, CB>>>(x4, p4, o4);
}